// round 10
// baseline (speedup 1.0000x reference)
#include <cuda_runtime.h>
#include <cuda_fp16.h>
#include <cstdint>

// Problem constants
constexpr int BB = 256;     // batch = M per CTA (full batch)
constexpr int H  = 1024;    // hidden
constexpr int L  = 10000;   // labels
constexpr int LPB = 16;     // labels per CTA (N = 128)
constexpr int KC = 64;      // K per chunk
constexpr int NCHUNK = H / KC;  // 16
constexpr int NSTAGE_A = 3;

// smem: A 3 stages x 32KB, then B 2 bufs x 16KB
constexpr int OFF_A = 0;
constexpr int A_STAGE = 32768;
constexpr int OFF_B = NSTAGE_A * A_STAGE;        // 98304
constexpr int B_BUF = 16384;
constexpr int SMEM_DYN = 1024 + OFF_B + 2 * B_BUF;   // 132096

// pre-converted fp16 embeddings [256][1024]
__device__ __align__(16) __half g_eA[BB * H];

// ---------------- helpers ----------------
__device__ __forceinline__ uint32_t smem_u32(const void* p) {
    uint32_t a;
    asm("{ .reg .u64 t; cvta.to.shared.u64 t, %1; cvt.u32.u64 %0, t; }" : "=r"(a) : "l"(p));
    return a;
}
__device__ __forceinline__ void cpasync16(uint32_t dst, const void* src) {
    asm volatile("cp.async.cg.shared.global [%0], [%1], 16;" :: "r"(dst), "l"(src));
}
#define CP_COMMIT() asm volatile("cp.async.commit_group;" ::: "memory")
#define CP_WAIT1()  asm volatile("cp.async.wait_group 1;" ::: "memory")
#define CP_WAIT0()  asm volatile("cp.async.wait_group 0;" ::: "memory")

__device__ __forceinline__ void ldsm4(uint32_t* r, uint32_t addr) {
    asm volatile("ldmatrix.sync.aligned.m8n8.x4.shared.b16 {%0,%1,%2,%3}, [%4];"
                 : "=r"(r[0]), "=r"(r[1]), "=r"(r[2]), "=r"(r[3]) : "r"(addr));
}
__device__ __forceinline__ void ldsm4t(uint32_t* r, uint32_t addr) {
    asm volatile("ldmatrix.sync.aligned.m8n8.x4.trans.shared.b16 {%0,%1,%2,%3}, [%4];"
                 : "=r"(r[0]), "=r"(r[1]), "=r"(r[2]), "=r"(r[3]) : "r"(addr));
}
__device__ __forceinline__ void mma16816(float* c, const uint32_t* a, const uint32_t* b) {
    asm volatile(
        "mma.sync.aligned.m16n8k16.row.col.f32.f16.f16.f32 "
        "{%0,%1,%2,%3}, {%4,%5,%6,%7}, {%8,%9}, {%0,%1,%2,%3};"
        : "+f"(c[0]), "+f"(c[1]), "+f"(c[2]), "+f"(c[3])
        : "r"(a[0]), "r"(a[1]), "r"(a[2]), "r"(a[3]), "r"(b[0]), "r"(b[1]));
}
__device__ __forceinline__ uint32_t pkh2(float x0, float x1) {
    __half2 h = __float22half2_rn(make_float2(x0, x1));
    return *reinterpret_cast<uint32_t*>(&h);
}

// ---------------- pre-kernel: emb fp32 -> fp16 ----------------
__global__ void cvt_emb_kernel(const float* __restrict__ emb) {
    int i = blockIdx.x * blockDim.x + threadIdx.x;   // 65536 float4s
    float4 v = reinterpret_cast<const float4*>(emb)[i];
    reinterpret_cast<uint2*>(g_eA)[i] = make_uint2(pkh2(v.x, v.y), pkh2(v.z, v.w));
}

// ---------------- main kernel ----------------
__global__ __launch_bounds__(512, 1)
void imec_hmma_kernel(const float* __restrict__ W1,
                      const float* __restrict__ b1,
                      const float* __restrict__ W2,
                      const float* __restrict__ b2,
                      float* __restrict__ out)
{
    extern __shared__ char smraw[];
    uint32_t sraw = smem_u32(smraw);
    uint32_t sb = (sraw + 1023u) & ~1023u;
    char* smc = smraw + (sb - sraw);

    const int tid  = threadIdx.x;
    const int lane = tid & 31;
    const int wid  = tid >> 5;        // 0..15
    const int wm   = wid & 3;         // warp M group: 64 rows each (4x64=256)
    const int wn   = wid >> 2;        // warp N group: 32 cols = 4 labels (4x32=128)

    const int l0 = blockIdx.x * LPB;

    // ---- A staging: thread -> (row, k-half), 128B swizzled rows ----
    const int ar = tid >> 1;          // 0..255
    const int ahalf = tid & 1;
    const char* aSrc = reinterpret_cast<const char*>(g_eA)
                     + (size_t)ar * (H * 2) + ahalf * 64;
    const uint32_t aDstBase = (uint32_t)(ar * 128);
    const uint32_t arx = (uint32_t)(ar & 7);

    // ---- B staging: warp = label; coalesced LDG.128 ----
    const float* bSrc = W1 + (size_t)(l0 + wid) * (H * 8);
    const uint32_t bDstBase = (uint32_t)(wid * 1024) + (uint32_t)(lane * 8);

    // ---- A fragment addresses (K-major, swizzled) ----
    uint32_t aOff[4], aXor[4];
#pragma unroll
    for (int mi = 0; mi < 4; ++mi) {
        int r = wm * 64 + mi * 16 + (lane & 15);
        aOff[mi] = (uint32_t)r * 128u;
        aXor[mi] = (uint32_t)(r & 7) << 4;
    }
    const uint32_t aKadd = (uint32_t)(lane >> 4) << 4;

    // ---- B fragment addresses (per-label 1KB MN-major blobs, trans ldsm) ----
    uint32_t bOff[2];
#pragma unroll
    for (int i = 0; i < 2; ++i)
        bOff[i] = (uint32_t)((wn * 4 + 2 * i + (lane >> 4)) * 1024 + (lane & 15) * 16);

    float acc[4][4][4];
#pragma unroll
    for (int mi = 0; mi < 4; ++mi)
#pragma unroll
        for (int ni = 0; ni < 4; ++ni)
#pragma unroll
            for (int k = 0; k < 4; ++k) acc[mi][ni][k] = 0.0f;

    // two B prefetch register buffers (2-chunk-ahead LDG)
    float4 bv[2][4];

    auto stageA = [&](int c) {
        const int p = c % NSTAGE_A;
        const uint32_t ad = sb + (uint32_t)(OFF_A + p * A_STAGE) + aDstBase;
        const char* as = aSrc + c * 128;
#pragma unroll
        for (int j = 0; j < 4; ++j) {
            uint32_t u = (uint32_t)(ahalf * 4 + j);
            cpasync16(ad + ((u ^ arx) << 4), as + j * 16);
        }
    };

    auto ldgB = [&](int c) {
        const float* s = bSrc + (size_t)c * (KC * 8);
        float4* dst = bv[c & 1];
#pragma unroll
        for (int j = 0; j < 4; ++j)
            dst[j] = *reinterpret_cast<const float4*>(s + j * 128 + lane * 4);
    };

    auto stsB = [&](int c) {
        const int p = c & 1;
        const float4* src = bv[c & 1];
        char* bd = smc + OFF_B + p * B_BUF + bDstBase;
#pragma unroll
        for (int j = 0; j < 4; ++j) {
            uint2 w = make_uint2(pkh2(src[j].x, src[j].y), pkh2(src[j].z, src[j].w));
            *reinterpret_cast<uint2*>(bd + j * 256) = w;
        }
    };

    auto compute = [&](int c) {
        const uint32_t bA = sb + (uint32_t)(OFF_A + (c % NSTAGE_A) * A_STAGE);
        const uint32_t bB = sb + (uint32_t)(OFF_B + (c & 1) * B_BUF);
#pragma unroll
        for (int ks = 0; ks < 4; ++ks) {
            const uint32_t koff = (uint32_t)ks * 32u;
            uint32_t a[4][4], b[2][4];
#pragma unroll
            for (int mi = 0; mi < 4; ++mi)
                ldsm4(a[mi], bA + aOff[mi] + ((koff + aKadd) ^ aXor[mi]));
#pragma unroll
            for (int i = 0; i < 2; ++i)
                ldsm4t(b[i], bB + bOff[i] + (uint32_t)ks * 256u);
#pragma unroll
            for (int mi = 0; mi < 4; ++mi)
#pragma unroll
                for (int i = 0; i < 2; ++i) {
                    mma16816(acc[mi][2 * i],     a[mi], &b[i][0]);
                    mma16816(acc[mi][2 * i + 1], a[mi], &b[i][2]);
                }
        }
    };

    // ---- pipeline prologue ----
    // B: ldg 0 and 1; sts 0 (both smem B bufs free). A: stage 0,1 via cp.async.
    ldgB(0);
    ldgB(1);
    stageA(0); CP_COMMIT();
    stageA(1); CP_COMMIT();
    stsB(0);
    CP_WAIT1();        // A(0) landed
    __syncthreads();

    // ---- main loop: all staging issued BEFORE compute; barrier-protected ----
    for (int c = 0; c < NCHUNK; ++c) {
        // At loop top (post-barrier): compute(c-1) has retired, so B buf (c+1)&1
        // and A stage (c+2)%3 are reusable. Issue all staging now; it retires
        // under compute(c)'s ~1500-cycle MMA/LDSM block.
        if (c + 2 < NCHUNK) ldgB(c + 2);               // into bv[(c)&1] (freed by stsB(c))
        if (c + 1 < NCHUNK) stsB(c + 1);               // from bv[(c+1)&1]
        if (c + 2 < NCHUNK) { stageA(c + 2); CP_COMMIT(); }

        compute(c);

        if (c + 1 < NCHUNK) {
            if (c + 2 < NCHUNK) { CP_WAIT1(); } else { CP_WAIT0(); }
        }
        __syncthreads();
    }

    // ---- epilogue: relu(h + b1) . W2 + b2, quad-reduce over d ----
    const int gid = lane >> 2;
    const int tq  = lane & 3;
#pragma unroll
    for (int ni = 0; ni < 4; ++ni) {
        const int l = l0 + wn * 4 + ni;
        float2 bbv = *reinterpret_cast<const float2*>(b1 + (size_t)l * 8 + tq * 2);
        float2 wwv = *reinterpret_cast<const float2*>(W2 + (size_t)l * 8 + tq * 2);
        const float b2v = __ldg(b2 + l);
#pragma unroll
        for (int mi = 0; mi < 4; ++mi) {
            float s0 = fmaxf(acc[mi][ni][0] + bbv.x, 0.0f) * wwv.x
                     + fmaxf(acc[mi][ni][1] + bbv.y, 0.0f) * wwv.y;
            float s1 = fmaxf(acc[mi][ni][2] + bbv.x, 0.0f) * wwv.x
                     + fmaxf(acc[mi][ni][3] + bbv.y, 0.0f) * wwv.y;
            s0 += __shfl_xor_sync(0xffffffffu, s0, 1);
            s0 += __shfl_xor_sync(0xffffffffu, s0, 2);
            s1 += __shfl_xor_sync(0xffffffffu, s1, 1);
            s1 += __shfl_xor_sync(0xffffffffu, s1, 2);
            if (tq == 0) {
                const int b = wm * 64 + mi * 16 + gid;
                out[(size_t)b * L + l]       = s0 + b2v;
                out[(size_t)(b + 8) * L + l] = s1 + b2v;
            }
        }
    }
}

extern "C" void kernel_launch(void* const* d_in, const int* in_sizes, int n_in,
                              void* d_out, int out_size)
{
    const float* emb = (const float*)d_in[0];  // [B, H]
    const float* W1  = (const float*)d_in[1];  // [L, H, 8]
    const float* b1  = (const float*)d_in[2];  // [L, 8]
    const float* W2  = (const float*)d_in[3];  // [L, 8]
    const float* b2  = (const float*)d_in[4];  // [L]
    float* out       = (float*)d_out;          // [B, L]

    cudaFuncSetAttribute(imec_hmma_kernel,
                         cudaFuncAttributeMaxDynamicSharedMemorySize, SMEM_DYN);

    cvt_emb_kernel<<<BB * H / 4 / 256, 256>>>(emb);
    imec_hmma_kernel<<<L / LPB, 512, SMEM_DYN>>>(W1, b1, W2, b2, out);
}

// round 11
// speedup vs baseline: 1.3703x; 1.3703x over previous
#include <cuda_runtime.h>
#include <cuda_fp16.h>
#include <cstdint>

// Problem constants
constexpr int BB = 256;     // batch = M per CTA (full batch)
constexpr int H  = 1024;    // hidden
constexpr int L  = 10000;   // labels
constexpr int LPB = 16;     // labels per CTA (N = 128)
constexpr int KC = 64;      // K per chunk
constexpr int NCHUNK = H / KC;  // 16
constexpr int NITER = NCHUNK / 2;   // 8 (two chunks per barrier)

// smem: A = 2 iter-stages x 64KB (each 2 sub-chunks x 32KB)
//       B = 2 iter-bufs  x 32KB (each 2 sub-chunks x 16KB)
constexpr int OFF_A = 0;
constexpr int OFF_B = 131072;
constexpr int SMEM_DYN = 1024 + 131072 + 65536;   // 197632

// pre-converted fp16 embeddings [256][1024]
__device__ __align__(16) __half g_eA[BB * H];

// ---------------- helpers ----------------
__device__ __forceinline__ uint32_t smem_u32(const void* p) {
    uint32_t a;
    asm("{ .reg .u64 t; cvta.to.shared.u64 t, %1; cvt.u32.u64 %0, t; }" : "=r"(a) : "l"(p));
    return a;
}
__device__ __forceinline__ void cpasync16(uint32_t dst, const void* src) {
    asm volatile("cp.async.cg.shared.global [%0], [%1], 16;" :: "r"(dst), "l"(src));
}
#define CP_COMMIT() asm volatile("cp.async.commit_group;" ::: "memory")
#define CP_WAIT0()  asm volatile("cp.async.wait_group 0;" ::: "memory")

__device__ __forceinline__ void ldsm4(uint32_t* r, uint32_t addr) {
    asm volatile("ldmatrix.sync.aligned.m8n8.x4.shared.b16 {%0,%1,%2,%3}, [%4];"
                 : "=r"(r[0]), "=r"(r[1]), "=r"(r[2]), "=r"(r[3]) : "r"(addr));
}
__device__ __forceinline__ void ldsm4t(uint32_t* r, uint32_t addr) {
    asm volatile("ldmatrix.sync.aligned.m8n8.x4.trans.shared.b16 {%0,%1,%2,%3}, [%4];"
                 : "=r"(r[0]), "=r"(r[1]), "=r"(r[2]), "=r"(r[3]) : "r"(addr));
}
__device__ __forceinline__ void mma16816(float* c, const uint32_t* a, const uint32_t* b) {
    asm volatile(
        "mma.sync.aligned.m16n8k16.row.col.f32.f16.f16.f32 "
        "{%0,%1,%2,%3}, {%4,%5,%6,%7}, {%8,%9}, {%0,%1,%2,%3};"
        : "+f"(c[0]), "+f"(c[1]), "+f"(c[2]), "+f"(c[3])
        : "r"(a[0]), "r"(a[1]), "r"(a[2]), "r"(a[3]), "r"(b[0]), "r"(b[1]));
}
__device__ __forceinline__ uint32_t pkh2(float x0, float x1) {
    __half2 h = __float22half2_rn(make_float2(x0, x1));
    return *reinterpret_cast<uint32_t*>(&h);
}

// ---------------- pre-kernel: emb fp32 -> fp16 ----------------
__global__ void cvt_emb_kernel(const float* __restrict__ emb) {
    int i = blockIdx.x * blockDim.x + threadIdx.x;   // 65536 float4s
    float4 v = reinterpret_cast<const float4*>(emb)[i];
    reinterpret_cast<uint2*>(g_eA)[i] = make_uint2(pkh2(v.x, v.y), pkh2(v.z, v.w));
}

// ---------------- main kernel ----------------
__global__ __launch_bounds__(512, 1)
void imec_hmma_kernel(const float* __restrict__ W1,
                      const float* __restrict__ b1,
                      const float* __restrict__ W2,
                      const float* __restrict__ b2,
                      float* __restrict__ out)
{
    extern __shared__ char smraw[];
    uint32_t sraw = smem_u32(smraw);
    uint32_t sb = (sraw + 1023u) & ~1023u;
    char* smc = smraw + (sb - sraw);

    const int tid  = threadIdx.x;
    const int lane = tid & 31;
    const int wid  = tid >> 5;        // 0..15
    const int wm   = wid & 3;         // warp M group: 64 rows each (4x64=256)
    const int wn   = wid >> 2;        // warp N group: 32 cols = 4 labels (4x32=128)

    const int l0 = blockIdx.x * LPB;

    // chunk -> smem base offsets (iter-stage by (c>>1)&1, sub-chunk by c&1)
    auto aBase = [&](int c) -> uint32_t {
        return (uint32_t)(OFF_A + ((c >> 1) & 1) * 65536 + (c & 1) * 32768);
    };
    auto bBase = [&](int c) -> uint32_t {
        return (uint32_t)(OFF_B + ((c >> 1) & 1) * 32768 + (c & 1) * 16384);
    };

    // ---- A staging: thread -> (row, k-half), 128B swizzled rows ----
    const int ar = tid >> 1;          // 0..255
    const int ahalf = tid & 1;
    const char* aSrc = reinterpret_cast<const char*>(g_eA)
                     + (size_t)ar * (H * 2) + ahalf * 64;
    const uint32_t aDstBase = (uint32_t)(ar * 128);
    const uint32_t arx = (uint32_t)(ar & 7);

    // ---- B staging: warp = label; coalesced LDG.128 ----
    const float* bSrc = W1 + (size_t)(l0 + wid) * (H * 8);
    const uint32_t bDstBase = (uint32_t)(wid * 1024) + (uint32_t)(lane * 8);

    // ---- A fragment addresses (K-major, swizzled) ----
    uint32_t aOff[4], aXor[4];
#pragma unroll
    for (int mi = 0; mi < 4; ++mi) {
        int r = wm * 64 + mi * 16 + (lane & 15);
        aOff[mi] = (uint32_t)r * 128u;
        aXor[mi] = (uint32_t)(r & 7) << 4;
    }
    const uint32_t aKadd = (uint32_t)(lane >> 4) << 4;

    // ---- B fragment addresses (per-label 1KB MN-major blobs, trans ldsm) ----
    uint32_t bOff[2];
#pragma unroll
    for (int i = 0; i < 2; ++i)
        bOff[i] = (uint32_t)((wn * 4 + 2 * i + (lane >> 4)) * 1024 + (lane & 15) * 16);

    float acc[4][4][4];
#pragma unroll
    for (int mi = 0; mi < 4; ++mi)
#pragma unroll
        for (int ni = 0; ni < 4; ++ni)
#pragma unroll
            for (int k = 0; k < 4; ++k) acc[mi][ni][k] = 0.0f;

    float4 bv[4];   // W1 prefetch: 4 coalesced LDG.128 (single buffer, reloaded mid-iter)

    auto stageA = [&](int c) {
        const uint32_t ad = sb + aBase(c) + aDstBase;
        const char* as = aSrc + c * 128;
#pragma unroll
        for (int j = 0; j < 4; ++j) {
            uint32_t u = (uint32_t)(ahalf * 4 + j);
            cpasync16(ad + ((u ^ arx) << 4), as + j * 16);
        }
    };

    auto ldgB = [&](int c) {
        const float* s = bSrc + (size_t)c * (KC * 8);
#pragma unroll
        for (int j = 0; j < 4; ++j)
            bv[j] = *reinterpret_cast<const float4*>(s + j * 128 + lane * 4);
    };

    auto stsB = [&](int c) {
        char* bd = smc + bBase(c) + bDstBase;
#pragma unroll
        for (int j = 0; j < 4; ++j) {
            uint2 w = make_uint2(pkh2(bv[j].x, bv[j].y), pkh2(bv[j].z, bv[j].w));
            *reinterpret_cast<uint2*>(bd + j * 256) = w;
        }
    };

    auto compute = [&](int c) {
        const uint32_t bA = sb + aBase(c);
        const uint32_t bB = sb + bBase(c);
#pragma unroll
        for (int ks = 0; ks < 4; ++ks) {
            const uint32_t koff = (uint32_t)ks * 32u;
            uint32_t a[4][4], b[2][4];
#pragma unroll
            for (int mi = 0; mi < 4; ++mi)
                ldsm4(a[mi], bA + aOff[mi] + ((koff + aKadd) ^ aXor[mi]));
#pragma unroll
            for (int i = 0; i < 2; ++i)
                ldsm4t(b[i], bB + bOff[i] + (uint32_t)ks * 256u);
#pragma unroll
            for (int mi = 0; mi < 4; ++mi)
#pragma unroll
                for (int i = 0; i < 2; ++i) {
                    mma16816(acc[mi][2 * i],     a[mi], &b[i][0]);
                    mma16816(acc[mi][2 * i + 1], a[mi], &b[i][2]);
                }
        }
    };

    // ---- pipeline prologue: fill iter-0 stage (chunks 0,1) ----
    stageA(0); stageA(1); CP_COMMIT();
    ldgB(0); stsB(0);
    ldgB(1); stsB(1);
    CP_WAIT0();
    __syncthreads();

    // ---- main loop: 2 chunks per barrier, R9-style staging order ----
    for (int it = 0; it < NITER; ++it) {
        const int c0 = 2 * it;
        const int c1 = c0 + 1;
        const bool more = (it + 1 < NITER);

        if (more) ldgB(c0 + 2);                 // LDG early, hidden under compute(c0)
        compute(c0);
        if (more) {
            stsB(c0 + 2);                        // consume bv, then reuse it
            stageA(c0 + 2); stageA(c1 + 2); CP_COMMIT();
            ldgB(c1 + 2);                        // hidden under compute(c1)
        }
        compute(c1);
        if (more) { stsB(c1 + 2); CP_WAIT0(); }
        __syncthreads();
    }

    // ---- epilogue: relu(h + b1) . W2 + b2, quad-reduce over d ----
    const int gid = lane >> 2;
    const int tq  = lane & 3;
#pragma unroll
    for (int ni = 0; ni < 4; ++ni) {
        const int l = l0 + wn * 4 + ni;
        float2 bbv = *reinterpret_cast<const float2*>(b1 + (size_t)l * 8 + tq * 2);
        float2 wwv = *reinterpret_cast<const float2*>(W2 + (size_t)l * 8 + tq * 2);
        const float b2v = __ldg(b2 + l);
#pragma unroll
        for (int mi = 0; mi < 4; ++mi) {
            float s0 = fmaxf(acc[mi][ni][0] + bbv.x, 0.0f) * wwv.x
                     + fmaxf(acc[mi][ni][1] + bbv.y, 0.0f) * wwv.y;
            float s1 = fmaxf(acc[mi][ni][2] + bbv.x, 0.0f) * wwv.x
                     + fmaxf(acc[mi][ni][3] + bbv.y, 0.0f) * wwv.y;
            s0 += __shfl_xor_sync(0xffffffffu, s0, 1);
            s0 += __shfl_xor_sync(0xffffffffu, s0, 2);
            s1 += __shfl_xor_sync(0xffffffffu, s1, 1);
            s1 += __shfl_xor_sync(0xffffffffu, s1, 2);
            if (tq == 0) {
                const int b = wm * 64 + mi * 16 + gid;
                out[(size_t)b * L + l]       = s0 + b2v;
                out[(size_t)(b + 8) * L + l] = s1 + b2v;
            }
        }
    }
}

extern "C" void kernel_launch(void* const* d_in, const int* in_sizes, int n_in,
                              void* d_out, int out_size)
{
    const float* emb = (const float*)d_in[0];  // [B, H]
    const float* W1  = (const float*)d_in[1];  // [L, H, 8]
    const float* b1  = (const float*)d_in[2];  // [L, 8]
    const float* W2  = (const float*)d_in[3];  // [L, 8]
    const float* b2  = (const float*)d_in[4];  // [L]
    float* out       = (float*)d_out;          // [B, L]

    cudaFuncSetAttribute(imec_hmma_kernel,
                         cudaFuncAttributeMaxDynamicSharedMemorySize, SMEM_DYN);

    cvt_emb_kernel<<<BB * H / 4 / 256, 256>>>(emb);
    imec_hmma_kernel<<<L / LPB, 512, SMEM_DYN>>>(W1, b1, W2, b2, out);
}

// round 12
// speedup vs baseline: 1.5453x; 1.1277x over previous
#include <cuda_runtime.h>
#include <cuda_fp16.h>
#include <cstdint>

// Problem constants
constexpr int BB = 256;     // batch
constexpr int H  = 1024;    // hidden
constexpr int L  = 10000;   // labels
constexpr int MT = 128;     // M per CTA
constexpr int LPB = 16;     // labels per CTA (N = 128)
constexpr int KC = 64;      // K per chunk
constexpr int NCHUNK = H / KC;  // 16
constexpr int NSTAGE_A = 3;

// smem: A 3 stages x 16KB, B 2 bufs x 16KB
constexpr int OFF_A = 0;
constexpr int A_STAGE = 16384;
constexpr int OFF_B = NSTAGE_A * A_STAGE;       // 49152
constexpr int B_BUF = 16384;
constexpr int SMEM_DYN = 1024 + OFF_B + 2 * B_BUF;   // 82944

// pre-converted fp16 embeddings [256][1024]
__device__ __align__(16) __half g_eA[BB * H];

// ---------------- helpers ----------------
__device__ __forceinline__ uint32_t smem_u32(const void* p) {
    uint32_t a;
    asm("{ .reg .u64 t; cvta.to.shared.u64 t, %1; cvt.u32.u64 %0, t; }" : "=r"(a) : "l"(p));
    return a;
}
__device__ __forceinline__ void cpasync16(uint32_t dst, const void* src) {
    asm volatile("cp.async.cg.shared.global [%0], [%1], 16;" :: "r"(dst), "l"(src));
}
#define CP_COMMIT() asm volatile("cp.async.commit_group;" ::: "memory")
#define CP_WAIT1()  asm volatile("cp.async.wait_group 1;" ::: "memory")
#define CP_WAIT0()  asm volatile("cp.async.wait_group 0;" ::: "memory")

__device__ __forceinline__ void ldsm4(uint32_t* r, uint32_t addr) {
    asm volatile("ldmatrix.sync.aligned.m8n8.x4.shared.b16 {%0,%1,%2,%3}, [%4];"
                 : "=r"(r[0]), "=r"(r[1]), "=r"(r[2]), "=r"(r[3]) : "r"(addr));
}
__device__ __forceinline__ void ldsm4t(uint32_t* r, uint32_t addr) {
    asm volatile("ldmatrix.sync.aligned.m8n8.x4.trans.shared.b16 {%0,%1,%2,%3}, [%4];"
                 : "=r"(r[0]), "=r"(r[1]), "=r"(r[2]), "=r"(r[3]) : "r"(addr));
}
__device__ __forceinline__ void mma16816(float* c, const uint32_t* a, const uint32_t* b) {
    asm volatile(
        "mma.sync.aligned.m16n8k16.row.col.f32.f16.f16.f32 "
        "{%0,%1,%2,%3}, {%4,%5,%6,%7}, {%8,%9}, {%0,%1,%2,%3};"
        : "+f"(c[0]), "+f"(c[1]), "+f"(c[2]), "+f"(c[3])
        : "r"(a[0]), "r"(a[1]), "r"(a[2]), "r"(a[3]), "r"(b[0]), "r"(b[1]));
}
__device__ __forceinline__ uint32_t pkh2(float x0, float x1) {
    __half2 h = __float22half2_rn(make_float2(x0, x1));
    return *reinterpret_cast<uint32_t*>(&h);
}

// ---------------- pre-kernel: emb fp32 -> fp16 ----------------
__global__ void cvt_emb_kernel(const float* __restrict__ emb) {
    int i = blockIdx.x * blockDim.x + threadIdx.x;   // 65536 float4s
    float4 v = reinterpret_cast<const float4*>(emb)[i];
    reinterpret_cast<uint2*>(g_eA)[i] = make_uint2(pkh2(v.x, v.y), pkh2(v.z, v.w));
}

// ---------------- main kernel ----------------
__global__ __launch_bounds__(256, 2)
void imec_hmma_kernel(const float* __restrict__ W1,
                      const float* __restrict__ b1,
                      const float* __restrict__ W2,
                      const float* __restrict__ b2,
                      float* __restrict__ out)
{
    extern __shared__ char smraw[];
    uint32_t sraw = smem_u32(smraw);
    uint32_t sb = (sraw + 1023u) & ~1023u;
    char* smc = smraw + (sb - sraw);

    const int tid  = threadIdx.x;
    const int lane = tid & 31;
    const int wid  = tid >> 5;        // 0..7
    const int wm   = wid & 1;         // warp M group: 64 rows each (2x64=128)
    const int wn   = wid >> 1;        // warp N group: 32 cols = 4 labels (4x32=128)

    const int lg = blockIdx.x >> 1;
    const int mt = blockIdx.x & 1;
    const int m0 = mt * MT;
    const int l0 = lg * LPB;

    // ---- A staging: thread -> (row, k-half), 128B swizzled rows ----
    const int ar = tid >> 1;          // 0..127
    const int ahalf = tid & 1;
    const char* aSrc = reinterpret_cast<const char*>(g_eA)
                     + (size_t)(m0 + ar) * (H * 2) + ahalf * 64;
    const uint32_t aDstBase = (uint32_t)(ar * 128);
    const uint32_t arx = (uint32_t)(ar & 7);

    // ---- B staging: warp owns 2 labels (2*wid, 2*wid+1); coalesced LDG.128 ----
    const float* bSrc0 = W1 + (size_t)(l0 + 2 * wid)     * (H * 8);
    const float* bSrc1 = W1 + (size_t)(l0 + 2 * wid + 1) * (H * 8);
    const uint32_t bDst0 = (uint32_t)((2 * wid)     * 1024) + (uint32_t)(lane * 8);
    const uint32_t bDst1 = (uint32_t)((2 * wid + 1) * 1024) + (uint32_t)(lane * 8);

    // ---- A fragment addresses (K-major, swizzled) ----
    uint32_t aOff[4], aXor[4];
#pragma unroll
    for (int mi = 0; mi < 4; ++mi) {
        int r = wm * 64 + mi * 16 + (lane & 15);
        aOff[mi] = (uint32_t)r * 128u;
        aXor[mi] = (uint32_t)(r & 7) << 4;
    }
    const uint32_t aKadd = (uint32_t)(lane >> 4) << 4;

    // ---- B fragment addresses (per-label 1KB MN-major blobs, trans ldsm) ----
    uint32_t bOff[2];
#pragma unroll
    for (int i = 0; i < 2; ++i)
        bOff[i] = (uint32_t)((wn * 4 + 2 * i + (lane >> 4)) * 1024 + (lane & 15) * 16);

    float acc[4][4][4];
#pragma unroll
    for (int mi = 0; mi < 4; ++mi)
#pragma unroll
        for (int ni = 0; ni < 4; ++ni)
#pragma unroll
            for (int k = 0; k < 4; ++k) acc[mi][ni][k] = 0.0f;

    float4 bv[4];   // B prefetch for ONE label (reused per half)

    auto stageA = [&](int c) {
        const uint32_t ad = sb + (uint32_t)(OFF_A + (c % NSTAGE_A) * A_STAGE) + aDstBase;
        const char* as = aSrc + c * 128;
#pragma unroll
        for (int j = 0; j < 4; ++j) {
            uint32_t u = (uint32_t)(ahalf * 4 + j);
            cpasync16(ad + ((u ^ arx) << 4), as + j * 16);
        }
    };

    auto ldgB = [&](int c, int h) {
        const float* s = (h == 0 ? bSrc0 : bSrc1) + (size_t)c * (KC * 8);
#pragma unroll
        for (int j = 0; j < 4; ++j)
            bv[j] = *reinterpret_cast<const float4*>(s + j * 128 + lane * 4);
    };

    auto stsB = [&](int c, int h) {
        char* bd = smc + OFF_B + (c & 1) * B_BUF + (h == 0 ? bDst0 : bDst1);
#pragma unroll
        for (int j = 0; j < 4; ++j) {
            uint2 w = make_uint2(pkh2(bv[j].x, bv[j].y), pkh2(bv[j].z, bv[j].w));
            *reinterpret_cast<uint2*>(bd + j * 256) = w;
        }
    };

    auto compute = [&](int c, int ks0, int ks1) {
        const uint32_t bA = sb + (uint32_t)(OFF_A + (c % NSTAGE_A) * A_STAGE);
        const uint32_t bB = sb + (uint32_t)(OFF_B + (c & 1) * B_BUF);
#pragma unroll
        for (int ks = ks0; ks < ks1; ++ks) {
            const uint32_t koff = (uint32_t)ks * 32u;
            uint32_t a[4][4], b[2][4];
#pragma unroll
            for (int mi = 0; mi < 4; ++mi)
                ldsm4(a[mi], bA + aOff[mi] + ((koff + aKadd) ^ aXor[mi]));
#pragma unroll
            for (int i = 0; i < 2; ++i)
                ldsm4t(b[i], bB + bOff[i] + (uint32_t)ks * 256u);
#pragma unroll
            for (int mi = 0; mi < 4; ++mi)
#pragma unroll
                for (int i = 0; i < 2; ++i) {
                    mma16816(acc[mi][2 * i],     a[mi], &b[i][0]);
                    mma16816(acc[mi][2 * i + 1], a[mi], &b[i][2]);
                }
        }
    };

    // ---- pipeline prologue ----
    stageA(0); CP_COMMIT();
    stageA(1); CP_COMMIT();
    ldgB(0, 0); stsB(0, 0);
    ldgB(0, 1); stsB(0, 1);
    CP_WAIT1();        // A(0) landed
    __syncthreads();

    // ---- main loop: R9 ordering, B staged in two label-halves around ks pairs ----
    for (int c = 0; c < NCHUNK; ++c) {
        const bool more = (c + 1 < NCHUNK);
        if (more) ldgB(c + 1, 0);            // label A LDG, hidden under ks0-1
        compute(c, 0, 2);
        if (more) { stsB(c + 1, 0); ldgB(c + 1, 1); }   // label B LDG under ks2-3
        compute(c, 2, 4);
        if (more) stsB(c + 1, 1);
        if (c + 2 < NCHUNK) { stageA(c + 2); CP_COMMIT(); }
        if (more) {
            if (c + 2 < NCHUNK) { CP_WAIT1(); } else { CP_WAIT0(); }
        }
        __syncthreads();
    }

    // ---- epilogue: relu(h + b1) . W2 + b2, quad-reduce over d ----
    const int gid = lane >> 2;
    const int tq  = lane & 3;
#pragma unroll
    for (int ni = 0; ni < 4; ++ni) {
        const int l = l0 + wn * 4 + ni;
        float2 bbv = *reinterpret_cast<const float2*>(b1 + (size_t)l * 8 + tq * 2);
        float2 wwv = *reinterpret_cast<const float2*>(W2 + (size_t)l * 8 + tq * 2);
        const float b2v = __ldg(b2 + l);
#pragma unroll
        for (int mi = 0; mi < 4; ++mi) {
            float s0 = fmaxf(acc[mi][ni][0] + bbv.x, 0.0f) * wwv.x
                     + fmaxf(acc[mi][ni][1] + bbv.y, 0.0f) * wwv.y;
            float s1 = fmaxf(acc[mi][ni][2] + bbv.x, 0.0f) * wwv.x
                     + fmaxf(acc[mi][ni][3] + bbv.y, 0.0f) * wwv.y;
            s0 += __shfl_xor_sync(0xffffffffu, s0, 1);
            s0 += __shfl_xor_sync(0xffffffffu, s0, 2);
            s1 += __shfl_xor_sync(0xffffffffu, s1, 1);
            s1 += __shfl_xor_sync(0xffffffffu, s1, 2);
            if (tq == 0) {
                const int b = m0 + wm * 64 + mi * 16 + gid;
                out[(size_t)b * L + l]       = s0 + b2v;
                out[(size_t)(b + 8) * L + l] = s1 + b2v;
            }
        }
    }
}

extern "C" void kernel_launch(void* const* d_in, const int* in_sizes, int n_in,
                              void* d_out, int out_size)
{
    const float* emb = (const float*)d_in[0];  // [B, H]
    const float* W1  = (const float*)d_in[1];  // [L, H, 8]
    const float* b1  = (const float*)d_in[2];  // [L, 8]
    const float* W2  = (const float*)d_in[3];  // [L, 8]
    const float* b2  = (const float*)d_in[4];  // [L]
    float* out       = (float*)d_out;          // [B, L]

    cudaFuncSetAttribute(imec_hmma_kernel,
                         cudaFuncAttributeMaxDynamicSharedMemorySize, SMEM_DYN);

    cvt_emb_kernel<<<BB * H / 4 / 256, 256>>>(emb);
    imec_hmma_kernel<<<(L / LPB) * 2, 256, SMEM_DYN>>>(W1, b1, W2, b2, out);
}